// round 9
// baseline (speedup 1.0000x reference)
#include <cuda_runtime.h>
#include <cstdint>
#define T_STEPS 200
typedef unsigned long long u64t;

__device__ float g_p[(size_t)T_STEPS * 1152 * 64];      // [t][k][b]
__device__ float g_s3[3 * 64 * 64 * 4];                  // [slot][k4][b][4]
__device__ float g_sr[2 * 64 * 256];                     // [buf][b][oc]
__device__ float g_sf[2 * 64 * 128];                     // [buf][b][row]
__device__ unsigned g_cnt[4 * 32];
__device__ unsigned g_gen[4 * 32];

__device__ __forceinline__ void gridbar_g(int grp, unsigned n) {
    __syncthreads();
    if (threadIdx.x == 0) {
        unsigned* cnt = &g_cnt[grp * 32];
        unsigned* gen = &g_gen[grp * 32];
        unsigned g;
        asm volatile("ld.acquire.gpu.u32 %0, [%1];" : "=r"(g) : "l"(gen));
        unsigned prev;
        asm volatile("atom.acq_rel.gpu.add.u32 %0, [%1], 1;"
                     : "=r"(prev) : "l"(cnt) : "memory");
        if (prev == n - 1u) {
            asm volatile("st.relaxed.gpu.u32 [%0], %1;" :: "l"(cnt), "r"(0u) : "memory");
            asm volatile("st.release.gpu.u32 [%0], %1;" :: "l"(gen), "r"(g + 1u) : "memory");
        } else {
            unsigned cur;
            do {
                asm volatile("ld.acquire.gpu.u32 %0, [%1];" : "=r"(cur) : "l"(gen));
            } while (cur == g);
        }
    }
    __syncthreads();
}
__device__ __forceinline__ u64t pk2(float lo, float hi) {
    u64t r; asm("mov.b64 %0, {%1, %2};" : "=l"(r) : "f"(lo), "f"(hi)); return r;
}
__device__ __forceinline__ void upk2(u64t v, float& lo, float& hi) {
    asm("mov.b64 {%0, %1}, %2;" : "=f"(lo), "=f"(hi) : "l"(v));
}
__device__ __forceinline__ u64t fma2(u64t a, u64t b, u64t c) {
    u64t d; asm("fma.rn.f32x2 %0, %1, %2, %3;" : "=l"(d) : "l"(a), "l"(b), "l"(c)); return d;
}
__device__ __forceinline__ unsigned smem_u32(const void* p) {
    unsigned a;
    asm("{ .reg .u64 t; cvta.to.shared.u64 t, %1; cvt.u32.u64 %0, t; }" : "=r"(a) : "l"(p));
    return a;
}
__device__ __forceinline__ void cp16(unsigned sdst, const void* gsrc) {
    asm volatile("cp.async.cg.shared.global [%0], [%1], 16;" :: "r"(sdst), "l"(gsrc));
}
#define CP_COMMIT() asm volatile("cp.async.commit_group;" ::: "memory")
template<int N> __device__ __forceinline__ void cp_wait() {
    asm volatile("cp.async.wait_group %0;" :: "n"(N) : "memory");
}
__device__ __forceinline__ void lif_update(float psp, float& cur, float& volt, float& spk) {
    cur  = __fadd_rn(__fmul_rn(0.5f, cur), psp);
    volt = __fadd_rn(__fmul_rn(__fmul_rn(0.75f, volt), __fadd_rn(1.f, -spk)), cur);
    spk  = (volt > 0.5f) ? 1.f : 0.f;
}

// ================= Phase A (R5, pool store -> [t][k][b]) =================
#define A_XS 0
#define A_W1S 100
#define A_B1S 676
#define A_B2S 740
#define A_S1S 804
#define A_S2S 4964
#define A_W2P 7268
#define A_TOT 44132
__global__ __launch_bounds__(128, 1)
void phaseA_kernel(const float* __restrict__ input,
                   const float* __restrict__ w1, const float* __restrict__ b1,
                   const float* __restrict__ w2, const float* __restrict__ b2)
{
    extern __shared__ float sm[];
    float* xs = sm + A_XS; float* w1s = sm + A_W1S; float* b1s = sm + A_B1S;
    float* b2s = sm + A_B2S; float* s1s = sm + A_S1S; float* s2s = sm + A_S2S;
    float* w2p = sm + A_W2P;
    const int tid = threadIdx.x;
    const int b = blockIdx.x >> 1, h = blockIdx.x & 1;
    for (int i = tid; i < 36864; i += 128) {
        int oc = i / 576, r = i - oc * 576;
        w2p[(r * 32 + (oc >> 1)) * 2 + (oc & 1)] = w2[h * 36864 + i];
    }
    for (int i = tid; i < 576; i += 128) w1s[i] = w1[i];
    if (tid < 64) { b1s[tid] = b1[tid]; b2s[tid] = b2[h * 64 + tid]; }
    for (int i = tid; i < 4160; i += 128) s1s[i] = 0.f;
    for (int i = tid; i < 2304; i += 128) s2s[i] = 0.f;
    __syncthreads();
    const int p = tid >> 2, q = tid & 3;
    const int qy = q >> 1, qx = q & 1;
    const int y0a = qy * 4, x0a = qx * 4, y0b = qy * 3, x0b = qx * 3;
    float c1[2][16], v1[2][16], c2[2][9], v2[2][9], sp2[2][9];
#pragma unroll
    for (int o = 0; o < 2; ++o) {
#pragma unroll
        for (int i = 0; i < 16; ++i) { c1[o][i] = 0.f; v1[o][i] = 0.f; }
#pragma unroll
        for (int i = 0; i < 9; ++i) { c2[o][i] = 0.f; v2[o][i] = 0.f; sp2[o][i] = 0.f; }
    }
    const float* xin = input + (size_t)b * 20000;
    for (int t = 0; t < T_STEPS; ++t) {
        if (tid < 100) xs[tid] = xin[tid * 200 + t];
        __syncthreads();
#pragma unroll
        for (int o = 0; o < 2; ++o) {
            const int occ = 2 * p + o;
            const float bb = b1s[occ];
            const float* wv = w1s + occ * 9;
#pragma unroll
            for (int iy = 0; iy < 4; ++iy)
#pragma unroll
                for (int ix = 0; ix < 4; ++ix) {
                    const int y = y0a + iy, x = x0a + ix;
                    float a = 0.f;
#pragma unroll
                    for (int ky = 0; ky < 3; ++ky)
#pragma unroll
                        for (int kx = 0; kx < 3; ++kx)
                            a = __fmaf_rn(xs[(y + ky) * 10 + (x + kx)], wv[ky * 3 + kx], a);
                    const float psp = __fadd_rn(a, bb);
                    const int i = iy * 4 + ix, sidx = occ * 65 + y * 8 + x;
                    float sp = s1s[sidx];
                    lif_update(psp, c1[o][i], v1[o][i], sp);
                    s1s[sidx] = sp;
                }
        }
        __syncthreads();
        {
            u64t acc[9];
#pragma unroll
            for (int j = 0; j < 9; ++j) acc[j] = 0ull;
#pragma unroll 2
            for (int ic = 0; ic < 64; ++ic) {
                u64t ins[5][5];
#pragma unroll
                for (int r = 0; r < 5; ++r)
#pragma unroll
                    for (int c = 0; c < 5; ++c) {
                        float v = s1s[ic * 65 + (y0b + r) * 8 + (x0b + c)];
                        ins[r][c] = pk2(v, v);
                    }
#pragma unroll
                for (int kk = 0; kk < 9; ++kk) {
                    const int ky = kk / 3, kx = kk % 3;
                    const u64t w = *(const u64t*)(w2p + ((ic * 9 + kk) * 32 + p) * 2);
#pragma unroll
                    for (int dy = 0; dy < 3; ++dy)
#pragma unroll
                        for (int dx = 0; dx < 3; ++dx)
                            acc[dy * 3 + dx] = fma2(ins[dy + ky][dx + kx], w, acc[dy * 3 + dx]);
                }
            }
#pragma unroll
            for (int j = 0; j < 9; ++j) {
                const int dy = j / 3, dx = j % 3;
                float alo, ahi; upk2(acc[j], alo, ahi);
#pragma unroll
                for (int o = 0; o < 2; ++o) {
                    const int occ = 2 * p + o;
                    const float psp = __fadd_rn(o ? ahi : alo, b2s[occ]);
                    lif_update(psp, c2[o][j], v2[o][j], sp2[o][j]);
                    s2s[occ * 36 + (y0b + dy) * 6 + (x0b + dx)] = sp2[o][j];
                }
            }
        }
        __syncthreads();
        for (int idx = tid; idx < 576; idx += 128) {
            int c = idx / 9, pos = idx - c * 9;
            int py = pos / 3, px = pos - py * 3;
            float v = 0.25f * ((s2s[c * 36 + (2 * py) * 6 + 2 * px]
                              + s2s[c * 36 + (2 * py) * 6 + 2 * px + 1])
                             + (s2s[c * 36 + (2 * py + 1) * 6 + 2 * px]
                              + s2s[c * 36 + (2 * py + 1) * 6 + 2 * px + 1]));
            int k = (h * 64 + c) * 9 + pos;
            g_p[((size_t)t * 1152 + k) * 64 + b] = v;
        }
    }
}

// ================= Phase B =================
#define B_W3S  0        // 18432 [k][16oc]
#define B_TCW  18432    // 12672 [i*16+ol][264]
#define B_RECW 31104    // 4224
#define B_F1W  35328    // 4224
#define B_B3   39552
#define B_TCB  39568
#define B_RECB 39616
#define B_F1B  39632
#define B_F2S  39648
#define B_TSW  39904    // 200
#define B_S3C  40104    // 12288 [slot][k4][b16][4]
#define B_CBUF 52392    // 3*1536 [buf][kl96][b16]
#define B_TOT  57000    // 228000 bytes

__device__ __forceinline__ float dot256g(const float* __restrict__ wr,
                                         const float* __restrict__ xr) {
    float4 x[16];
#pragma unroll
    for (int j = 0; j < 8; ++j) x[j] = __ldcg((const float4*)(xr + j * 4));
    float a = 0.f;
#pragma unroll
    for (int g = 0; g < 8; ++g) {
        const int cb = (g & 1) * 8, nb = ((g + 1) & 1) * 8;
        if (g < 7) {
#pragma unroll
            for (int j = 0; j < 8; ++j)
                x[nb + j] = __ldcg((const float4*)(xr + ((g + 1) * 8 + j) * 4));
        }
#pragma unroll
        for (int j = 0; j < 8; ++j) {
            float4 w = *(const float4*)(wr + (g * 8 + j) * 4);
            a = __fmaf_rn(w.x, x[cb + j].x, a);
            a = __fmaf_rn(w.y, x[cb + j].y, a);
            a = __fmaf_rn(w.z, x[cb + j].z, a);
            a = __fmaf_rn(w.w, x[cb + j].w, a);
        }
    }
    return a;
}
__device__ __forceinline__ float dot128g(const float* __restrict__ wr,
                                         const float* __restrict__ xr) {
    float4 x[16];
#pragma unroll
    for (int j = 0; j < 8; ++j) x[j] = __ldcg((const float4*)(xr + j * 4));
    float a = 0.f;
#pragma unroll
    for (int g = 0; g < 4; ++g) {
        const int cb = (g & 1) * 8, nb = ((g + 1) & 1) * 8;
        if (g < 3) {
#pragma unroll
            for (int j = 0; j < 8; ++j)
                x[nb + j] = __ldcg((const float4*)(xr + ((g + 1) * 8 + j) * 4));
        }
#pragma unroll
        for (int j = 0; j < 8; ++j) {
            float4 w = *(const float4*)(wr + (g * 8 + j) * 4);
            a = __fmaf_rn(w.x, x[cb + j].x, a);
            a = __fmaf_rn(w.y, x[cb + j].y, a);
            a = __fmaf_rn(w.z, x[cb + j].z, a);
            a = __fmaf_rn(w.w, x[cb + j].w, a);
        }
    }
    return a;
}

__global__ __launch_bounds__(256, 1)
void phaseB_kernel(const float* __restrict__ w3, const float* __restrict__ b3,
                   const float* __restrict__ tcw, const float* __restrict__ tcb,
                   const float* __restrict__ recw, const float* __restrict__ recb,
                   const float* __restrict__ f1w, const float* __restrict__ f1b,
                   const float* __restrict__ f2w, const float* __restrict__ tsw,
                   float* __restrict__ out)
{
    extern __shared__ float sm[];
    float* w3s = sm + B_W3S; float* tcws = sm + B_TCW; float* recws = sm + B_RECW;
    float* f1ws = sm + B_F1W; float* b3s = sm + B_B3; float* tcbs = sm + B_TCB;
    float* recbs = sm + B_RECB; float* f1bs = sm + B_F1B; float* f2s = sm + B_F2S;
    float* tsws = sm + B_TSW; float* s3c = sm + B_S3C; float* cbuf = sm + B_CBUF;

    const int tid = threadIdx.x;
    const int og = blockIdx.x >> 2, bg = blockIdx.x & 3;
    const int ol = tid >> 4, bl = tid & 15;
    const int b = bg * 16 + bl;
    const bool cons = (tid < 128);
    const int cw = tid >> 5, l = tid & 31;
    const int ocl = l & 15;                 // consumer oc local
    const int bp = (cw << 1) | (l >> 4);    // consumer batch pair 0..7
    const int pid = tid - 128;              // producer index
    const unsigned smb = smem_u32(sm);

    // ---- one-time staging ----
    for (int g = tid; g < 18432; g += 256) {
        int k = g >> 4, o = g & 15;
        w3s[g] = w3[(size_t)(og * 16 + o) * 1152 + k];
    }
    for (int g = tid; g < 3 * 16 * 256; g += 256) {
        int i = g >> 12, r = g & 4095, o = r >> 8, k = r & 255;
        tcws[(i * 16 + o) * 264 + k] = tcw[i * 65536 + (og * 16 + o) * 256 + k];
    }
    for (int g = tid; g < 4096; g += 256) {
        int o = g >> 8, k = g & 255;
        recws[o * 264 + k] = recw[(og * 16 + o) * 256 + k];
        if (og < 8) f1ws[o * 264 + k] = f1w[(og * 16 + o) * 256 + k];
    }
    if (tid < 16) {
        b3s[tid] = b3[og * 16 + tid];
        recbs[tid] = recb[og * 16 + tid];
        if (og < 8) f1bs[tid] = f1b[og * 16 + tid];
    }
    if (tid < 48) tcbs[tid] = tcb[(tid >> 4) * 256 + og * 16 + (tid & 15)];
    f2s[tid] = f2w[tid];
    for (int g = tid; g < 200; g += 256) tsws[g] = tsw[g];
    __syncthreads();

    float cur3a = 0.f, volt3a = 0.f, spk3a = 0.f;
    float cur3b = 0.f, volt3b = 0.f, spk3b = 0.f;
    float curt = 0.f, voltt = 0.f, spkt = 0.f;
    float curr = 0.f, voltr = 0.f, spkr = 0.f;
    float curf = 0.f, voltf = 0.f, spkf = 0.f;
    float outacc = 0.f;

    // producer chunk stage: chunk c (96 k) of tb -> cbuf[buf]
    auto stage = [&](const float* tb, int c, int buf) {
#pragma unroll
        for (int j = 0; j < 3; ++j) {
            int idx = pid * 3 + j;                 // 0..383 float4s
            int kl = idx >> 2, b4 = idx & 3;
            const float* src = tb + (size_t)(c * 96 + kl) * 64 + b4 * 4;
            unsigned dst = smb + (unsigned)(B_CBUF + buf * 1536 + kl * 16 + b4 * 4) * 4u;
            cp16(dst, src);
        }
        CP_COMMIT();
    };

    // prologue: chunks 0,1 of t=0
    {
        const float* tb0 = g_p + bg * 16;
        if (!cons) { stage(tb0, 0, 0); stage(tb0, 1, 1); cp_wait<1>(); }
    }
    __syncthreads();

    for (int t = 0; t < T_STEPS; ++t) {
        const float* tb  = g_p + (size_t)t * 73728 + bg * 16;
        const float* tb1 = g_p + (size_t)(t + 1) * 73728 + bg * 16;

        // ---------- conv3: 12 chunks, fma2 over batch pairs ----------
        u64t acc = 0ull;
        for (int c = 0; c < 12; ++c) {
            if (cons) {
                const float* xb = cbuf + (c % 3) * 1536 + bp * 2;
                const float* wb = w3s + c * 96 * 16 + ocl;
#pragma unroll 12
                for (int kl = 0; kl < 96; ++kl) {
                    u64t x = *(const u64t*)(xb + kl * 16);
                    float w = wb[kl * 16];
                    acc = fma2(x, pk2(w, w), acc);
                }
            } else {
                const int cc = c + 2;
                if (cc < 12)            { stage(tb,  cc,      cc % 3); cp_wait<1>(); }
                else if (t + 1 < T_STEPS){ stage(tb1, cc - 12, cc % 3); cp_wait<1>(); }
                else                    { cp_wait<0>(); }
            }
            __syncthreads();
        }
        if (cons) {
            float alo, ahi; upk2(acc, alo, ahi);
            lif_update(__fadd_rn(alo, b3s[ocl]), cur3a, volt3a, spk3a);
            lif_update(__fadd_rn(ahi, b3s[ocl]), cur3b, volt3b, spk3b);
            const int oc = og * 16 + ocl;
            const int k4 = oc >> 2, sub = oc & 3;
            const int b0 = bg * 16 + 2 * bp;
            g_s3[((t % 3) * 64 + k4) * 256 + b0 * 4 + sub]       = spk3a;
            g_s3[((t % 3) * 64 + k4) * 256 + (b0 + 1) * 4 + sub] = spk3b;
        }
        gridbar_g(bg, 16);   // ---- bar 1 ----

        // ---------- stage fresh s3 slot (consumers, cp.async) ----------
        if (cons) {
            const int slot = t % 3;
#pragma unroll
            for (int j = 0; j < 8; ++j) {
                int i = tid * 8 + j, k4 = i >> 4, b2 = i & 15;
                const float* src = g_s3 + (slot * 64 + k4) * 256 + (bg * 16 + b2) * 4;
                unsigned dst = smb + (unsigned)(B_S3C + slot * 4096 + (k4 * 16 + b2) * 4) * 4u;
                cp16(dst, src);
            }
            CP_COMMIT();
            cp_wait<0>();
        }
        __syncthreads();

        // ---------- tc (SMEM) + rec (global contiguous), all 256 ----------
        {
            const float* x0 = s3c + (t % 3) * 4096 + bl * 4;
            const float* x1 = s3c + ((t + 2) % 3) * 4096 + bl * 4;
            const float* x2 = s3c + ((t + 1) % 3) * 4096 + bl * 4;
            const float* w0 = tcws + (0 * 16 + ol) * 264;
            const float* w1v = tcws + (1 * 16 + ol) * 264;
            const float* w2v = tcws + (2 * 16 + ol) * 264;
            const bool h1 = (t >= 1), h2 = (t >= 2);
            float d0 = 0.f, d1 = 0.f, d2 = 0.f;
#pragma unroll 8
            for (int k4 = 0; k4 < 64; ++k4) {
                float4 a0 = *(const float4*)(x0 + k4 * 64);
                float4 q0 = *(const float4*)(w0 + k4 * 4);
                d0 = __fmaf_rn(q0.x, a0.x, d0); d0 = __fmaf_rn(q0.y, a0.y, d0);
                d0 = __fmaf_rn(q0.z, a0.z, d0); d0 = __fmaf_rn(q0.w, a0.w, d0);
                if (h1) {
                    float4 a1 = *(const float4*)(x1 + k4 * 64);
                    float4 q1 = *(const float4*)(w1v + k4 * 4);
                    d1 = __fmaf_rn(q1.x, a1.x, d1); d1 = __fmaf_rn(q1.y, a1.y, d1);
                    d1 = __fmaf_rn(q1.z, a1.z, d1); d1 = __fmaf_rn(q1.w, a1.w, d1);
                }
                if (h2) {
                    float4 a2 = *(const float4*)(x2 + k4 * 64);
                    float4 q2 = *(const float4*)(w2v + k4 * 4);
                    d2 = __fmaf_rn(q2.x, a2.x, d2); d2 = __fmaf_rn(q2.y, a2.y, d2);
                    d2 = __fmaf_rn(q2.z, a2.z, d2); d2 = __fmaf_rn(q2.w, a2.w, d2);
                }
            }
            float a = __fadd_rn(0.f, __fadd_rn(d0, tcbs[ol]));
            if (h1) a = __fadd_rn(a, __fadd_rn(d1, tcbs[16 + ol]));
            if (h2) a = __fadd_rn(a, __fadd_rn(d2, tcbs[32 + ol]));
            lif_update(a, curt, voltt, spkt);

            float dotr = 0.f;
            if (t > 0)
                dotr = dot256g(recws + ol * 264, g_sr + ((t & 1) ^ 1) * 16384 + b * 256);
            const float pr = __fadd_rn(__fadd_rn(spkt, dotr), recbs[ol]);
            lif_update(pr, curr, voltr, spkr);
            g_sr[(t & 1) * 16384 + b * 256 + og * 16 + ol] = spkr;
        }
        gridbar_g(bg, 16);   // ---- bar 2 ----

        // ---------- fc1 (og<8) / fc2(t-1) (og15) ----------
        if (og < 8) {
            const float d = dot256g(f1ws + ol * 264, g_sr + (t & 1) * 16384 + b * 256);
            lif_update(__fadd_rn(d, f1bs[ol]), curf, voltf, spkf);
            g_sf[(t & 1) * 8192 + b * 128 + og * 16 + ol] = spkf;
        } else if (og == 15 && tid < 32 && t >= 1) {
            const int o = tid >> 4, bb = bg * 16 + (tid & 15);
            const float d = dot128g(f2s + o * 128, g_sf + ((t - 1) & 1) * 8192 + bb * 128);
            outacc = __fadd_rn(outacc, __fmul_rn(d, tsws[t - 1]));
        }
    }

    gridbar_g(bg, 16);
    if (og == 15 && tid < 32) {
        const int o = tid >> 4, bb = bg * 16 + (tid & 15);
        const float d = dot128g(f2s + o * 128, g_sf + ((T_STEPS - 1) & 1) * 8192 + bb * 128);
        outacc = __fadd_rn(outacc, __fmul_rn(d, tsws[T_STEPS - 1]));
        out[bb * 2 + o] = outacc;
    }
}

extern "C" void kernel_launch(void* const* d_in, const int* in_sizes, int n_in,
                              void* d_out, int out_size)
{
    (void)in_sizes; (void)n_in; (void)out_size;
    const float* input = (const float*)d_in[0];
    const float* w1 = (const float*)d_in[1];
    const float* b1 = (const float*)d_in[2];
    const float* w2 = (const float*)d_in[3];
    const float* b2 = (const float*)d_in[4];
    const float* w3 = (const float*)d_in[5];
    const float* b3 = (const float*)d_in[6];
    const float* tcw = (const float*)d_in[7];
    const float* tcb = (const float*)d_in[8];
    const float* recw = (const float*)d_in[9];
    const float* recb = (const float*)d_in[10];
    const float* f1w = (const float*)d_in[11];
    const float* f1b = (const float*)d_in[12];
    const float* f2w = (const float*)d_in[13];
    const float* tsw = (const float*)d_in[14];
    float* out = (float*)d_out;

    cudaFuncSetAttribute(phaseA_kernel, cudaFuncAttributeMaxDynamicSharedMemorySize,
                         A_TOT * sizeof(float));
    cudaFuncSetAttribute(phaseB_kernel, cudaFuncAttributeMaxDynamicSharedMemorySize,
                         B_TOT * sizeof(float));
    phaseA_kernel<<<128, 128, A_TOT * sizeof(float)>>>(input, w1, b1, w2, b2);
    phaseB_kernel<<<64, 256, B_TOT * sizeof(float)>>>(w3, b3, tcw, tcb, recw, recb,
                                                      f1w, f1b, f2w, tsw, out);
}

// round 10
// speedup vs baseline: 1.7713x; 1.7713x over previous
#include <cuda_runtime.h>
#include <cstdint>
#define T_STEPS 200
typedef unsigned long long u64t;

__device__ float g_p[(size_t)T_STEPS * 288 * 64 * 4];   // [t][k4][b][4]
__device__ float g_s3[3 * 64 * 64 * 4];                  // [slot][k4][b][4]
__device__ float g_sr[2 * 64 * 64 * 4];                  // [buf][k4][b][4] (k=oc 256)
__device__ float g_sf[2 * 32 * 64 * 4];                  // [buf][k4][b][4] (k=row 128)
__device__ unsigned g_cnt[8 * 32];
__device__ unsigned g_gen[8 * 32];

__device__ __forceinline__ void gridbar_g(int grp, unsigned n) {
    __syncthreads();
    if (threadIdx.x == 0) {
        unsigned* cnt = &g_cnt[grp * 32];
        unsigned* gen = &g_gen[grp * 32];
        unsigned g;
        asm volatile("ld.acquire.gpu.u32 %0, [%1];" : "=r"(g) : "l"(gen));
        unsigned prev;
        asm volatile("atom.acq_rel.gpu.add.u32 %0, [%1], 1;"
                     : "=r"(prev) : "l"(cnt) : "memory");
        if (prev == n - 1u) {
            asm volatile("st.relaxed.gpu.u32 [%0], %1;" :: "l"(cnt), "r"(0u) : "memory");
            asm volatile("st.release.gpu.u32 [%0], %1;" :: "l"(gen), "r"(g + 1u) : "memory");
        } else {
            unsigned cur;
            do {
                asm volatile("ld.acquire.gpu.u32 %0, [%1];" : "=r"(cur) : "l"(gen));
            } while (cur == g);
        }
    }
    __syncthreads();
}
__device__ __forceinline__ u64t pk2(float lo, float hi) {
    u64t r; asm("mov.b64 %0, {%1, %2};" : "=l"(r) : "f"(lo), "f"(hi)); return r;
}
__device__ __forceinline__ void upk2(u64t v, float& lo, float& hi) {
    asm("mov.b64 {%0, %1}, %2;" : "=f"(lo), "=f"(hi) : "l"(v));
}
__device__ __forceinline__ u64t fma2(u64t a, u64t b, u64t c) {
    u64t d; asm("fma.rn.f32x2 %0, %1, %2, %3;" : "=l"(d) : "l"(a), "l"(b), "l"(c)); return d;
}
__device__ __forceinline__ unsigned smem_u32(const void* p) {
    unsigned a;
    asm("{ .reg .u64 t; cvta.to.shared.u64 t, %1; cvt.u32.u64 %0, t; }" : "=r"(a) : "l"(p));
    return a;
}
__device__ __forceinline__ void cp16(unsigned sdst, const void* gsrc) {
    asm volatile("cp.async.cg.shared.global [%0], [%1], 16;" :: "r"(sdst), "l"(gsrc));
}
#define CP_COMMIT() asm volatile("cp.async.commit_group;" ::: "memory")
template<int N> __device__ __forceinline__ void cp_wait() {
    asm volatile("cp.async.wait_group %0;" :: "n"(N) : "memory");
}
__device__ __forceinline__ void lif_update(float psp, float& cur, float& volt, float& spk) {
    cur  = __fadd_rn(__fmul_rn(0.5f, cur), psp);
    volt = __fadd_rn(__fmul_rn(__fmul_rn(0.75f, volt), __fadd_rn(1.f, -spk)), cur);
    spk  = (volt > 0.5f) ? 1.f : 0.f;
}

// ================= Phase A (R5, unchanged) =================
#define A_XS 0
#define A_W1S 100
#define A_B1S 676
#define A_B2S 740
#define A_S1S 804
#define A_S2S 4964
#define A_W2P 7268
#define A_TOT 44132
__global__ __launch_bounds__(128, 1)
void phaseA_kernel(const float* __restrict__ input,
                   const float* __restrict__ w1, const float* __restrict__ b1,
                   const float* __restrict__ w2, const float* __restrict__ b2)
{
    extern __shared__ float sm[];
    float* xs = sm + A_XS; float* w1s = sm + A_W1S; float* b1s = sm + A_B1S;
    float* b2s = sm + A_B2S; float* s1s = sm + A_S1S; float* s2s = sm + A_S2S;
    float* w2p = sm + A_W2P;
    const int tid = threadIdx.x;
    const int b = blockIdx.x >> 1, h = blockIdx.x & 1;
    for (int i = tid; i < 36864; i += 128) {
        int oc = i / 576, r = i - oc * 576;
        w2p[(r * 32 + (oc >> 1)) * 2 + (oc & 1)] = w2[h * 36864 + i];
    }
    for (int i = tid; i < 576; i += 128) w1s[i] = w1[i];
    if (tid < 64) { b1s[tid] = b1[tid]; b2s[tid] = b2[h * 64 + tid]; }
    for (int i = tid; i < 4160; i += 128) s1s[i] = 0.f;
    for (int i = tid; i < 2304; i += 128) s2s[i] = 0.f;
    __syncthreads();
    const int p = tid >> 2, q = tid & 3;
    const int qy = q >> 1, qx = q & 1;
    const int y0a = qy * 4, x0a = qx * 4, y0b = qy * 3, x0b = qx * 3;
    float c1[2][16], v1[2][16], c2[2][9], v2[2][9], sp2[2][9];
#pragma unroll
    for (int o = 0; o < 2; ++o) {
#pragma unroll
        for (int i = 0; i < 16; ++i) { c1[o][i] = 0.f; v1[o][i] = 0.f; }
#pragma unroll
        for (int i = 0; i < 9; ++i) { c2[o][i] = 0.f; v2[o][i] = 0.f; sp2[o][i] = 0.f; }
    }
    const float* xin = input + (size_t)b * 20000;
    for (int t = 0; t < T_STEPS; ++t) {
        if (tid < 100) xs[tid] = xin[tid * 200 + t];
        __syncthreads();
#pragma unroll
        for (int o = 0; o < 2; ++o) {
            const int occ = 2 * p + o;
            const float bb = b1s[occ];
            const float* wv = w1s + occ * 9;
#pragma unroll
            for (int iy = 0; iy < 4; ++iy)
#pragma unroll
                for (int ix = 0; ix < 4; ++ix) {
                    const int y = y0a + iy, x = x0a + ix;
                    float a = 0.f;
#pragma unroll
                    for (int ky = 0; ky < 3; ++ky)
#pragma unroll
                        for (int kx = 0; kx < 3; ++kx)
                            a = __fmaf_rn(xs[(y + ky) * 10 + (x + kx)], wv[ky * 3 + kx], a);
                    const float psp = __fadd_rn(a, bb);
                    const int i = iy * 4 + ix, sidx = occ * 65 + y * 8 + x;
                    float sp = s1s[sidx];
                    lif_update(psp, c1[o][i], v1[o][i], sp);
                    s1s[sidx] = sp;
                }
        }
        __syncthreads();
        {
            u64t acc[9];
#pragma unroll
            for (int j = 0; j < 9; ++j) acc[j] = 0ull;
#pragma unroll 2
            for (int ic = 0; ic < 64; ++ic) {
                u64t ins[5][5];
#pragma unroll
                for (int r = 0; r < 5; ++r)
#pragma unroll
                    for (int c = 0; c < 5; ++c) {
                        float v = s1s[ic * 65 + (y0b + r) * 8 + (x0b + c)];
                        ins[r][c] = pk2(v, v);
                    }
#pragma unroll
                for (int kk = 0; kk < 9; ++kk) {
                    const int ky = kk / 3, kx = kk % 3;
                    const u64t w = *(const u64t*)(w2p + ((ic * 9 + kk) * 32 + p) * 2);
#pragma unroll
                    for (int dy = 0; dy < 3; ++dy)
#pragma unroll
                        for (int dx = 0; dx < 3; ++dx)
                            acc[dy * 3 + dx] = fma2(ins[dy + ky][dx + kx], w, acc[dy * 3 + dx]);
                }
            }
#pragma unroll
            for (int j = 0; j < 9; ++j) {
                const int dy = j / 3, dx = j % 3;
                float alo, ahi; upk2(acc[j], alo, ahi);
#pragma unroll
                for (int o = 0; o < 2; ++o) {
                    const int occ = 2 * p + o;
                    const float psp = __fadd_rn(o ? ahi : alo, b2s[occ]);
                    lif_update(psp, c2[o][j], v2[o][j], sp2[o][j]);
                    s2s[occ * 36 + (y0b + dy) * 6 + (x0b + dx)] = sp2[o][j];
                }
            }
        }
        __syncthreads();
        for (int idx = tid; idx < 576; idx += 128) {
            int c = idx / 9, pos = idx - c * 9;
            int py = pos / 3, px = pos - py * 3;
            float v = 0.25f * ((s2s[c * 36 + (2 * py) * 6 + 2 * px]
                              + s2s[c * 36 + (2 * py) * 6 + 2 * px + 1])
                             + (s2s[c * 36 + (2 * py + 1) * 6 + 2 * px]
                              + s2s[c * 36 + (2 * py + 1) * 6 + 2 * px + 1]));
            int k = (h * 64 + c) * 9 + pos;
            g_p[(size_t)t * 73728 + (size_t)(k >> 2) * 256 + b * 4 + (k & 3)] = v;
        }
    }
}

// ================= Phase B: 128 CTAs (og16 x bg8), 128 threads =================
#define B_W3S  0        // 18432 [k][16]
#define B_TCW  18432    // 12672
#define B_RECW 31104    // 4224
#define B_F1W  35328    // 4224
#define B_B3   39552    // 16
#define B_TCB  39568    // 48
#define B_RECB 39616    // 16
#define B_F1B  39632    // 16
#define B_F2S  39648    // 256
#define B_TSW  39904    // 200
#define B_S3C  40104    // 3*2048 [slot][k4][bl8][4]
#define B_PB   46248    // 3*1024 [buf][k4l32][bl8][4]
#define B_TOT  49320    // 197280 bytes

// serial dot over k=256, x strided 256 floats per k4, ldcg + ping-pong prefetch
__device__ __forceinline__ float dot256s(const float* __restrict__ wr,
                                         const float* __restrict__ xr) {
    float4 x[16];
#pragma unroll
    for (int j = 0; j < 8; ++j) x[j] = __ldcg((const float4*)(xr + j * 256));
    float a = 0.f;
#pragma unroll
    for (int g = 0; g < 8; ++g) {
        const int cb = (g & 1) * 8, nb = ((g + 1) & 1) * 8;
        if (g < 7) {
#pragma unroll
            for (int j = 0; j < 8; ++j)
                x[nb + j] = __ldcg((const float4*)(xr + ((g + 1) * 8 + j) * 256));
        }
#pragma unroll
        for (int j = 0; j < 8; ++j) {
            float4 w = *(const float4*)(wr + (g * 8 + j) * 4);
            a = __fmaf_rn(w.x, x[cb + j].x, a);
            a = __fmaf_rn(w.y, x[cb + j].y, a);
            a = __fmaf_rn(w.z, x[cb + j].z, a);
            a = __fmaf_rn(w.w, x[cb + j].w, a);
        }
    }
    return a;
}
// serial dot over k=128, x strided 256 per k4
__device__ __forceinline__ float dot128s(const float* __restrict__ wr,
                                         const float* __restrict__ xr) {
    float4 x[16];
#pragma unroll
    for (int j = 0; j < 8; ++j) x[j] = __ldcg((const float4*)(xr + j * 256));
    float a = 0.f;
#pragma unroll
    for (int g = 0; g < 4; ++g) {
        const int cb = (g & 1) * 8, nb = ((g + 1) & 1) * 8;
        if (g < 3) {
#pragma unroll
            for (int j = 0; j < 8; ++j)
                x[nb + j] = __ldcg((const float4*)(xr + ((g + 1) * 8 + j) * 256));
        }
#pragma unroll
        for (int j = 0; j < 8; ++j) {
            float4 w = *(const float4*)(wr + (g * 8 + j) * 4);
            a = __fmaf_rn(w.x, x[cb + j].x, a);
            a = __fmaf_rn(w.y, x[cb + j].y, a);
            a = __fmaf_rn(w.z, x[cb + j].z, a);
            a = __fmaf_rn(w.w, x[cb + j].w, a);
        }
    }
    return a;
}

__global__ __launch_bounds__(128, 1)
void phaseB_kernel(const float* __restrict__ w3, const float* __restrict__ b3,
                   const float* __restrict__ tcw, const float* __restrict__ tcb,
                   const float* __restrict__ recw, const float* __restrict__ recb,
                   const float* __restrict__ f1w, const float* __restrict__ f1b,
                   const float* __restrict__ f2w, const float* __restrict__ tsw,
                   float* __restrict__ out)
{
    extern __shared__ float sm[];
    float* w3s = sm + B_W3S; float* tcws = sm + B_TCW; float* recws = sm + B_RECW;
    float* f1ws = sm + B_F1W; float* b3s = sm + B_B3; float* tcbs = sm + B_TCB;
    float* recbs = sm + B_RECB; float* f1bs = sm + B_F1B; float* f2s = sm + B_F2S;
    float* tsws = sm + B_TSW; float* s3c = sm + B_S3C; float* pb = sm + B_PB;

    const int tid = threadIdx.x;
    const int og = blockIdx.x >> 3, bg = blockIdx.x & 7;
    const int ol = tid >> 3, bl = tid & 7;       // 16 oc x 8 b
    const int b = bg * 8 + bl;
    const int oc = og * 16 + ol;
    const unsigned smb = smem_u32(sm);

    // ---- one-time staging ----
    for (int g = tid; g < 18432; g += 128) {
        int k = g >> 4, o = g & 15;
        w3s[g] = w3[(size_t)(og * 16 + o) * 1152 + k];
    }
    for (int g = tid; g < 3 * 16 * 256; g += 128) {
        int i = g >> 12, r = g & 4095, o = r >> 8, k = r & 255;
        tcws[(i * 16 + o) * 264 + k] = tcw[i * 65536 + (og * 16 + o) * 256 + k];
    }
    for (int g = tid; g < 4096; g += 128) {
        int o = g >> 8, k = g & 255;
        recws[o * 264 + k] = recw[(og * 16 + o) * 256 + k];
        if (og < 8) f1ws[o * 264 + k] = f1w[(og * 16 + o) * 256 + k];
    }
    if (tid < 16) {
        b3s[tid] = b3[og * 16 + tid];
        recbs[tid] = recb[og * 16 + tid];
        if (og < 8) f1bs[tid] = f1b[og * 16 + tid];
    }
    if (tid < 48) tcbs[tid] = tcb[(tid >> 4) * 256 + og * 16 + (tid & 15)];
    for (int g = tid; g < 256; g += 128) f2s[g] = f2w[g];
    for (int g = tid; g < 200; g += 128) tsws[g] = tsw[g];
    __syncthreads();

    float cur3 = 0.f, volt3 = 0.f, spk3 = 0.f;
    float curt = 0.f, voltt = 0.f, spkt = 0.f;
    float curr = 0.f, voltr = 0.f, spkr = 0.f;
    float curf = 0.f, voltf = 0.f, spkf = 0.f;
    float outacc = 0.f;

    // conv3 chunk staging: chunk c = 32 k4 groups; 256 float4 / 128 thr = 2 each
    auto stage = [&](int t, int c, int buf) {
#pragma unroll
        for (int j = 0; j < 2; ++j) {
            int idx = tid * 2 + j;                // 0..255
            int k4l = idx >> 3, b2 = idx & 7;
            const float* src = g_p + (size_t)t * 73728
                             + (size_t)(c * 32 + k4l) * 256 + (bg * 8 + b2) * 4;
            unsigned dst = smb + (unsigned)(B_PB + buf * 1024 + (k4l * 8 + b2) * 4) * 4u;
            cp16(dst, src);
        }
        CP_COMMIT();
    };

    stage(0, 0, 0);
    stage(0, 1, 1);

    for (int t = 0; t < T_STEPS; ++t) {
        // ---------- conv3: 9 chunks, serial FMA chain from SMEM ----------
        float a3 = 0.f;
        for (int c = 0; c < 9; ++c) {
            if (c + 2 <= 8) cp_wait<1>(); else cp_wait<0>();
            __syncthreads();
            if (c + 2 <= 8) stage(t, c + 2, (c + 2) % 3);
            const float* xb = pb + (c % 3) * 1024;
            const float* wb = w3s + c * 128 * 16 + ol;
#pragma unroll
            for (int k4l = 0; k4l < 32; ++k4l) {
                float4 x = *(const float4*)(xb + (k4l * 8 + bl) * 4);
                a3 = __fmaf_rn(wb[(k4l * 4 + 0) * 16], x.x, a3);
                a3 = __fmaf_rn(wb[(k4l * 4 + 1) * 16], x.y, a3);
                a3 = __fmaf_rn(wb[(k4l * 4 + 2) * 16], x.z, a3);
                a3 = __fmaf_rn(wb[(k4l * 4 + 3) * 16], x.w, a3);
            }
        }
        // prefetch chunks 0,1 of t+1 (overlaps tc/rec/fc1 + barriers)
        if (t + 1 < T_STEPS) { stage(t + 1, 0, 0); stage(t + 1, 1, 1); }

        lif_update(__fadd_rn(a3, b3s[ol]), cur3, volt3, spk3);
        g_s3[((t % 3) * 64 + (oc >> 2)) * 256 + b * 4 + (oc & 3)] = spk3;
        gridbar_g(bg, 16);   // ---- bar 1 ----

        // ---------- stage fresh s3 slot into SMEM (cp.async) ----------
        {
            const int slot = t % 3;
#pragma unroll
            for (int j = 0; j < 4; ++j) {
                int i = tid * 4 + j;               // 0..511
                int k4 = i >> 3, b2 = i & 7;
                const float* src = g_s3 + (slot * 64 + k4) * 256 + (bg * 8 + b2) * 4;
                unsigned dst = smb + (unsigned)(B_S3C + slot * 2048 + (k4 * 8 + b2) * 4) * 4u;
                cp16(dst, src);
            }
            CP_COMMIT();
            cp_wait<0>();
        }
        __syncthreads();

        // ---------- tc (SMEM) + rec ----------
        {
            const float* x0 = s3c + (t % 3) * 2048 + bl * 4;
            const float* x1 = s3c + ((t + 2) % 3) * 2048 + bl * 4;
            const float* x2 = s3c + ((t + 1) % 3) * 2048 + bl * 4;
            const float* w0 = tcws + (0 * 16 + ol) * 264;
            const float* w1v = tcws + (1 * 16 + ol) * 264;
            const float* w2v = tcws + (2 * 16 + ol) * 264;
            const bool h1 = (t >= 1), h2 = (t >= 2);
            float d0 = 0.f, d1 = 0.f, d2 = 0.f;
#pragma unroll 8
            for (int k4 = 0; k4 < 64; ++k4) {
                float4 a0 = *(const float4*)(x0 + k4 * 32);
                float4 q0 = *(const float4*)(w0 + k4 * 4);
                d0 = __fmaf_rn(q0.x, a0.x, d0); d0 = __fmaf_rn(q0.y, a0.y, d0);
                d0 = __fmaf_rn(q0.z, a0.z, d0); d0 = __fmaf_rn(q0.w, a0.w, d0);
                if (h1) {
                    float4 a1 = *(const float4*)(x1 + k4 * 32);
                    float4 q1 = *(const float4*)(w1v + k4 * 4);
                    d1 = __fmaf_rn(q1.x, a1.x, d1); d1 = __fmaf_rn(q1.y, a1.y, d1);
                    d1 = __fmaf_rn(q1.z, a1.z, d1); d1 = __fmaf_rn(q1.w, a1.w, d1);
                }
                if (h2) {
                    float4 a2 = *(const float4*)(x2 + k4 * 32);
                    float4 q2 = *(const float4*)(w2v + k4 * 4);
                    d2 = __fmaf_rn(q2.x, a2.x, d2); d2 = __fmaf_rn(q2.y, a2.y, d2);
                    d2 = __fmaf_rn(q2.z, a2.z, d2); d2 = __fmaf_rn(q2.w, a2.w, d2);
                }
            }
            float a = __fadd_rn(0.f, __fadd_rn(d0, tcbs[ol]));
            if (h1) a = __fadd_rn(a, __fadd_rn(d1, tcbs[16 + ol]));
            if (h2) a = __fadd_rn(a, __fadd_rn(d2, tcbs[32 + ol]));
            lif_update(a, curt, voltt, spkt);

            float dotr = 0.f;
            if (t > 0)
                dotr = dot256s(recws + ol * 264, g_sr + ((t & 1) ^ 1) * 16384 + b * 4);
            const float pr = __fadd_rn(__fadd_rn(spkt, dotr), recbs[ol]);
            lif_update(pr, curr, voltr, spkr);
            g_sr[((t & 1) * 64 + (oc >> 2)) * 256 + b * 4 + (oc & 3)] = spkr;
        }
        gridbar_g(bg, 16);   // ---- bar 2 ----

        // ---------- fc1 (og<8) / fc2(t-1) (og15) ----------
        if (og < 8) {
            const float d = dot256s(f1ws + ol * 264, g_sr + (t & 1) * 16384 + b * 4);
            lif_update(__fadd_rn(d, f1bs[ol]), curf, voltf, spkf);
            const int row = og * 16 + ol;
            g_sf[((t & 1) * 32 + (row >> 2)) * 256 + b * 4 + (row & 3)] = spkf;
        } else if (og == 15 && tid < 16 && t >= 1) {
            const int o = tid >> 3, bb = bg * 8 + (tid & 7);
            const float d = dot128s(f2s + o * 128,
                                    g_sf + ((t - 1) & 1) * 8192 + bb * 4);
            outacc = __fadd_rn(outacc, __fmul_rn(d, tsws[t - 1]));
        }
    }

    gridbar_g(bg, 16);   // order fc1(199) writes
    if (og == 15 && tid < 16) {
        const int o = tid >> 3, bb = bg * 8 + (tid & 7);
        const float d = dot128s(f2s + o * 128,
                                g_sf + ((T_STEPS - 1) & 1) * 8192 + bb * 4);
        outacc = __fadd_rn(outacc, __fmul_rn(d, tsws[T_STEPS - 1]));
        out[bb * 2 + o] = outacc;
    }
}

extern "C" void kernel_launch(void* const* d_in, const int* in_sizes, int n_in,
                              void* d_out, int out_size)
{
    (void)in_sizes; (void)n_in; (void)out_size;
    const float* input = (const float*)d_in[0];
    const float* w1 = (const float*)d_in[1];
    const float* b1 = (const float*)d_in[2];
    const float* w2 = (const float*)d_in[3];
    const float* b2 = (const float*)d_in[4];
    const float* w3 = (const float*)d_in[5];
    const float* b3 = (const float*)d_in[6];
    const float* tcw = (const float*)d_in[7];
    const float* tcb = (const float*)d_in[8];
    const float* recw = (const float*)d_in[9];
    const float* recb = (const float*)d_in[10];
    const float* f1w = (const float*)d_in[11];
    const float* f1b = (const float*)d_in[12];
    const float* f2w = (const float*)d_in[13];
    const float* tsw = (const float*)d_in[14];
    float* out = (float*)d_out;

    cudaFuncSetAttribute(phaseA_kernel, cudaFuncAttributeMaxDynamicSharedMemorySize,
                         A_TOT * sizeof(float));
    cudaFuncSetAttribute(phaseB_kernel, cudaFuncAttributeMaxDynamicSharedMemorySize,
                         B_TOT * sizeof(float));
    phaseA_kernel<<<128, 128, A_TOT * sizeof(float)>>>(input, w1, b1, w2, b2);
    phaseB_kernel<<<128, 128, B_TOT * sizeof(float)>>>(w3, b3, tcw, tcb, recw, recb,
                                                       f1w, f1b, f2w, tsw, out);
}